// round 15
// baseline (speedup 1.0000x reference)
#include <cuda_runtime.h>
#include <cuda_fp16.h>
#include <cstdint>

// ---------------------------------------------------------------------------
// PatternCWanRoPE R15: ONE fused kernel = K/V prep (producer blocks) + flash
// attention (consumer blocks) overlapped via global release/acquire flags.
//   - 200 prep blocks (bid 0..199): RoPE(K)+convert V into fp16 scratch,
//     chunk-major (all bh's chunk 0 first), flag per (chunk,bh) unit.
//   - 1024 attn blocks (bid 200..1223): R14 attention (fp16 warp-MMA FA,
//     Q RoPE fused, register P-pass, cp.async double buffer, f16x2 exp,
//     MMA row-sums); acquire-spins on the producer flag before each
//     cp.async prefetch. Prologue fully hidden behind attention.
//   - trailing tiny kernel re-zeroes flags for graph replay.
//   q,k,v : (B=2, S=2048, H=16, D=128) fp32   freqs : (1,S,1,D)
//   out   : (B,H,S,D) fp32
// ---------------------------------------------------------------------------

#define B_ 2
#define S_ 2048
#define H_ 16
#define D_ 128
#define BH_ 32

#define BM 64
#define BN 64
#define NTHREADS 128
#define NPREP 200                 // < 296 wave-1 slots -> all resident, no deadlock
#define NUNITS 1024               // 32 chunks x 32 bh

#define KPITCH_B 272              // 136 halves/row (128 data + 8 pad); 17x16B
#define TILE_B   (64 * KPITCH_B)  // 17408 bytes per K or V tile
#define OFF_K0   0
#define OFF_K1   TILE_B
#define OFF_V0   (2 * TILE_B)
#define OFF_V1   (3 * TILE_B)     // ALSO the Q staging area before cp(1)
#define SMEM_BYTES (4 * TILE_B)   // 69632

#define ONES_H2 0x3C003C00u       // half2(1.0, 1.0)

// fp16 scratch in (B,H,S,D): rope'd K, V. (Q never round-trips.)
__device__ __half g_k[(size_t)BH_ * S_ * D_];
__device__ __half g_v[(size_t)BH_ * S_ * D_];
// producer flags, unit u = chunk*32 + bh. Statically zero; re-zeroed per call.
__device__ int g_flag[NUNITS];

// ---------------------------------------------------------------------------
__device__ __forceinline__ uint32_t smem_u32(const void* p) {
    uint32_t a;
    asm("{ .reg .u64 t; cvta.to.shared.u64 t, %1; cvt.u32.u64 %0, t; }"
        : "=r"(a) : "l"(p));
    return a;
}
__device__ __forceinline__ float fast_exp2(float x) {
    float y; asm("ex2.approx.f32 %0, %1;" : "=f"(y) : "f"(x));
    return y;
}
__device__ __forceinline__ uint32_t ex2_h2(uint32_t x) {
    uint32_t y; asm("ex2.approx.f16x2 %0, %1;" : "=r"(y) : "r"(x));
    return y;
}
__device__ __forceinline__ uint32_t h2pack(float a, float b) {
    __half2 h = __floats2half2_rn(a, b);
    return *reinterpret_cast<uint32_t*>(&h);
}
__device__ __forceinline__ void ldsm_x4(uint32_t r[4], uint32_t a) {
    asm volatile("ldmatrix.sync.aligned.m8n8.x4.shared.b16 {%0,%1,%2,%3}, [%4];"
                 : "=r"(r[0]), "=r"(r[1]), "=r"(r[2]), "=r"(r[3]) : "r"(a));
}
__device__ __forceinline__ void ldsm_x4_t(uint32_t r[4], uint32_t a) {
    asm volatile("ldmatrix.sync.aligned.m8n8.x4.trans.shared.b16 {%0,%1,%2,%3}, [%4];"
                 : "=r"(r[0]), "=r"(r[1]), "=r"(r[2]), "=r"(r[3]) : "r"(a));
}
__device__ __forceinline__ void mma_f16(float c[4], const uint32_t a[4],
                                        uint32_t b0, uint32_t b1) {
    asm volatile(
        "mma.sync.aligned.m16n8k16.row.col.f32.f16.f16.f32 "
        "{%0,%1,%2,%3}, {%4,%5,%6,%7}, {%8,%9}, {%0,%1,%2,%3};\n"
        : "+f"(c[0]), "+f"(c[1]), "+f"(c[2]), "+f"(c[3])
        : "r"(a[0]), "r"(a[1]), "r"(a[2]), "r"(a[3]), "r"(b0), "r"(b1));
}
#define CP_COMMIT() asm volatile("cp.async.commit_group;" ::: "memory")
#define CP_WAIT0()  asm volatile("cp.async.wait_group 0;" ::: "memory")

// Producer flag wait: acquire-spin, then order the following cp.async
// (async proxy) after the acquired data.
__device__ __forceinline__ void wait_flag(int u) {
    int v;
    asm volatile("ld.global.acquire.gpu.b32 %0, [%1];"
                 : "=r"(v) : "l"(g_flag + u) : "memory");
    while (!v) {
        __nanosleep(64);
        asm volatile("ld.global.acquire.gpu.b32 %0, [%1];"
                     : "=r"(v) : "l"(g_flag + u) : "memory");
    }
    asm volatile("fence.proxy.async;" ::: "memory");
}

// Prefetch one 64x128 fp16 K tile + V tile into SMEM buffers (one group).
__device__ __forceinline__ void cp_tile(const __half* __restrict__ Kg,
                                        const __half* __restrict__ Vg,
                                        uint32_t kbuf, uint32_t vbuf,
                                        int n0, int tid) {
#pragma unroll
    for (int i = 0; i < 8; i++) {
        int idx = tid + i * 128;
        int r = idx >> 4, c = idx & 15;
        uint32_t d = (uint32_t)(r * KPITCH_B + c * 16);
        asm volatile("cp.async.cg.shared.global [%0], [%1], 16;"
                     :: "r"(kbuf + d), "l"(Kg + (size_t)(n0 + r) * D_ + c * 8));
        asm volatile("cp.async.cg.shared.global [%0], [%1], 16;"
                     :: "r"(vbuf + d), "l"(Vg + (size_t)(n0 + r) * D_ + c * 8));
    }
    CP_COMMIT();
}

// ---------------------------------------------------------------------------
// Fused kernel. bid < NPREP: producer. Else: attention consumer.
// ---------------------------------------------------------------------------
__global__ void __launch_bounds__(NTHREADS, 2)
fused_kernel(float* __restrict__ out,
             const float* __restrict__ qf,
             const float* __restrict__ kf,
             const float* __restrict__ vf,
             const float* __restrict__ fr) {
    const int bid = blockIdx.x;
    const int tid = threadIdx.x;

    // ======================= PRODUCER PATH ================================
    if (bid < NPREP) {
        for (int u = bid; u < NUNITS; u += NPREP) {
            const int bh = u & 31, chunk = u >> 5;
            const int b = bh >> 4, h = bh & 15;
            const int s0 = chunk * 64;
#pragma unroll
            for (int it = 0; it < 8; it++) {
                int idx = tid + it * 128;
                int r = idx >> 4, c8 = idx & 15;
                int s = s0 + r;
                size_t in_off  = ((((size_t)b * S_ + s) * H_ + h) * D_) + c8 * 8;
                size_t f_off   = (size_t)s * D_ + c8 * 8;
                size_t out_off = ((size_t)bh * S_ + s) * D_ + c8 * 8;

                float4 f0 = *(const float4*)(fr + f_off);
                float4 f1 = *(const float4*)(fr + f_off + 4);
                float4 k0 = __ldcs((const float4*)(kf + in_off));
                float4 k1 = __ldcs((const float4*)(kf + in_off + 4));
                float4 v0 = __ldcs((const float4*)(vf + in_off));
                float4 v1 = __ldcs((const float4*)(vf + in_off + 4));

                uint4 ok, ov;
                ok.x = h2pack(f0.x * k0.x - f0.y * k0.y, f0.y * k0.x + f0.x * k0.y);
                ok.y = h2pack(f0.z * k0.z - f0.w * k0.w, f0.w * k0.z + f0.z * k0.w);
                ok.z = h2pack(f1.x * k1.x - f1.y * k1.y, f1.y * k1.x + f1.x * k1.y);
                ok.w = h2pack(f1.z * k1.z - f1.w * k1.w, f1.w * k1.z + f1.z * k1.w);
                ov.x = h2pack(v0.x, v0.y);
                ov.y = h2pack(v0.z, v0.w);
                ov.z = h2pack(v1.x, v1.y);
                ov.w = h2pack(v1.z, v1.w);

                *(uint4*)(g_k + out_off) = ok;
                *(uint4*)(g_v + out_off) = ov;
            }
            __syncthreads();
            if (tid == 0) {
                __threadfence();
                asm volatile("st.global.release.gpu.b32 [%0], %1;"
                             :: "l"(g_flag + u), "r"(1) : "memory");
            }
        }
        return;
    }

    // ======================= CONSUMER PATH (attention) =====================
    extern __shared__ __align__(16) char smem[];
    const uint32_t sb = smem_u32(smem);

    const int aidx = bid - NPREP;
    const int bh = aidx & 31;
    const int qt = 31 - (aidx >> 5);          // long rows first
    const int m0 = qt * BM;
    const int warp = tid >> 5;
    const int lane = tid & 31;
    const int g  = lane >> 2;
    const int t4 = lane & 3;
    const int b  = bh >> 4, h = bh & 15;

    const __half* Kg = g_k + (size_t)bh * S_ * D_;
    const __half* Vg = g_v + (size_t)bh * S_ * D_;

    // Tile 0 must be produced before the first prefetch.
    wait_flag(bh);                 // u = 0*32 + bh
    cp_tile(Kg, Vg, sb + OFF_K0, sb + OFF_V0, 0, tid);

    // ---- Q RoPE fused: fp32 q tile -> rope+scale -> fp16 into V1 staging ----
    {
        const float QS = 0.08838834764831845f * 1.4426950408889634f;
#pragma unroll
        for (int i = 0; i < 8; i++) {
            int idx = tid + i * 128;
            int r = idx >> 4, c8 = idx & 15;
            size_t qoff = ((((size_t)b * S_ + (m0 + r)) * H_ + h) * D_) + c8 * 8;
            size_t foff = (size_t)(m0 + r) * D_ + c8 * 8;
            float4 x0 = __ldcs((const float4*)(qf + qoff));
            float4 x1 = __ldcs((const float4*)(qf + qoff + 4));
            float4 f0 = *(const float4*)(fr + foff);
            float4 f1 = *(const float4*)(fr + foff + 4);
            uint4 o;
            o.x = h2pack((f0.x * x0.x - f0.y * x0.y) * QS,
                         (f0.y * x0.x + f0.x * x0.y) * QS);
            o.y = h2pack((f0.z * x0.z - f0.w * x0.w) * QS,
                         (f0.w * x0.z + f0.z * x0.w) * QS);
            o.z = h2pack((f1.x * x1.x - f1.y * x1.y) * QS,
                         (f1.y * x1.x + f1.x * x1.y) * QS);
            o.w = h2pack((f1.z * x1.z - f1.w * x1.w) * QS,
                         (f1.w * x1.z + f1.z * x1.w) * QS);
            *(uint4*)(smem + OFF_V1 + r * KPITCH_B + c8 * 16) = o;
        }
    }
    __syncthreads();   // Q visible to all warps

    const uint32_t qaddr = sb + OFF_V1 + (warp * 16 + (lane & 15)) * KPITCH_B
                         + (lane >> 4) * 16;
    uint32_t qa[8][4];
#pragma unroll
    for (int kfr = 0; kfr < 8; kfr++) ldsm_x4(qa[kfr], qaddr + kfr * 32);

    const uint32_t koff = ((lane >> 4) * 8 + (lane & 7)) * KPITCH_B
                        + ((lane >> 3) & 1) * 16;
    const uint32_t voff = (((lane >> 3) & 1) * 8 + (lane & 7)) * KPITCH_B
                        + (lane >> 4) * 16;

    float oacc[16][4];
#pragma unroll
    for (int i = 0; i < 16; i++) {
        oacc[i][0] = 0.f; oacc[i][1] = 0.f; oacc[i][2] = 0.f; oacc[i][3] = 0.f;
    }
    float sumA[4] = {0.f, 0.f, 0.f, 0.f};
    float sumB[4] = {0.f, 0.f, 0.f, 0.f};
    const int rl0 = warp * 16 + g;
    float mrow0 = -1e30f, mrow1 = -1e30f;

    const int ntiles = qt + 1;
    for (int t = 0; t < ntiles; t++) {
        const uint32_t kb   = (t & 1) ? OFF_K1 : OFF_K0;
        const uint32_t vb_o = (t & 1) ? OFF_V1 : OFF_V0;

        // ---- Single barrier point per tile ----
        CP_WAIT0();
        __syncthreads();
        if (t + 1 < ntiles) {
            wait_flag((t + 1) * 32 + bh);
            cp_tile(Kg, Vg, sb + ((t & 1) ? OFF_K0 : OFF_K1),
                    sb + ((t & 1) ? OFF_V0 : OFF_V1), (t + 1) * BN, tid);
        }

        const uint32_t kbase = sb + kb + koff;
        const uint32_t vbase = sb + vb_o + voff;

        // ---- S = Q K^T : kf OUTER so each sacc's RAW distance is 8 MMAs ----
        float sacc[8][4];
#pragma unroll
        for (int i = 0; i < 8; i++) {
            sacc[i][0] = 0.f; sacc[i][1] = 0.f; sacc[i][2] = 0.f; sacc[i][3] = 0.f;
        }
#pragma unroll
        for (int kfr = 0; kfr < 8; kfr++) {
#pragma unroll
            for (int np = 0; np < 4; np++) {
                uint32_t bfr[4];
                ldsm_x4(bfr, kbase + np * (16 * KPITCH_B) + kfr * 32);
                mma_f16(sacc[2 * np],     qa[kfr], bfr[0], bfr[1]);
                mma_f16(sacc[2 * np + 1], qa[kfr], bfr[2], bfr[3]);
            }
        }

        // ---- Causal mask (diagonal tile only) ----
        if (t == qt) {
#pragma unroll
            for (int nf = 0; nf < 8; nf++) {
                int c0 = nf * 8 + 2 * t4;
                if (c0     > rl0)     sacc[nf][0] = -1e30f;
                if (c0 + 1 > rl0)     sacc[nf][1] = -1e30f;
                if (c0     > rl0 + 8) sacc[nf][2] = -1e30f;
                if (c0 + 1 > rl0 + 8) sacc[nf][3] = -1e30f;
            }
        }

        // ---- Online softmax: row max via quad shuffle ----
        float tm0 = -1e30f, tm1 = -1e30f;
#pragma unroll
        for (int nf = 0; nf < 8; nf++) {
            tm0 = fmaxf(tm0, fmaxf(sacc[nf][0], sacc[nf][1]));
            tm1 = fmaxf(tm1, fmaxf(sacc[nf][2], sacc[nf][3]));
        }
        tm0 = fmaxf(tm0, __shfl_xor_sync(0xffffffffu, tm0, 1));
        tm0 = fmaxf(tm0, __shfl_xor_sync(0xffffffffu, tm0, 2));
        tm1 = fmaxf(tm1, __shfl_xor_sync(0xffffffffu, tm1, 1));
        tm1 = fmaxf(tm1, __shfl_xor_sync(0xffffffffu, tm1, 2));

        // Alpha-skip: rescale O / sums only when the running max increases.
        if (tm0 > mrow0 || tm1 > mrow1) {
            float mn0 = fmaxf(mrow0, tm0);
            float mn1 = fmaxf(mrow1, tm1);
            float alpha0 = fast_exp2(mrow0 - mn0);
            float alpha1 = fast_exp2(mrow1 - mn1);
            mrow0 = mn0; mrow1 = mn1;
            sumA[0] *= alpha0; sumA[2] *= alpha1;
            sumB[0] *= alpha0; sumB[2] *= alpha1;
#pragma unroll
            for (int nf = 0; nf < 16; nf++) {
                oacc[nf][0] *= alpha0; oacc[nf][1] *= alpha0;
                oacc[nf][2] *= alpha1; oacc[nf][3] *= alpha1;
            }
        }

        // ---- P = exp2(S - m) via ex2.approx.f16x2 -> PV A-fragments ----
        uint32_t paf[4][4];
#pragma unroll
        for (int kfr = 0; kfr < 4; kfr++) {
            paf[kfr][0] = ex2_h2(h2pack(sacc[2 * kfr][0] - mrow0,
                                        sacc[2 * kfr][1] - mrow0));
            paf[kfr][1] = ex2_h2(h2pack(sacc[2 * kfr][2] - mrow1,
                                        sacc[2 * kfr][3] - mrow1));
            paf[kfr][2] = ex2_h2(h2pack(sacc[2 * kfr + 1][0] - mrow0,
                                        sacc[2 * kfr + 1][1] - mrow0));
            paf[kfr][3] = ex2_h2(h2pack(sacc[2 * kfr + 1][2] - mrow1,
                                        sacc[2 * kfr + 1][3] - mrow1));
        }

        // ---- Row sums on the tensor pipe (interleaved accumulators) ----
        mma_f16(sumA, paf[0], ONES_H2, ONES_H2);
        mma_f16(sumB, paf[1], ONES_H2, ONES_H2);
        mma_f16(sumA, paf[2], ONES_H2, ONES_H2);
        mma_f16(sumB, paf[3], ONES_H2, ONES_H2);

        // ---- O += P V ----
#pragma unroll
        for (int kfr = 0; kfr < 4; kfr++) {
#pragma unroll
            for (int np = 0; np < 8; np++) {
                uint32_t vb[4];
                ldsm_x4_t(vb, vbase + kfr * (16 * KPITCH_B) + np * 32);
                mma_f16(oacc[2 * np],     paf[kfr], vb[0], vb[1]);
                mma_f16(oacc[2 * np + 1], paf[kfr], vb[2], vb[3]);
            }
        }
        // no trailing barrier: next iteration's top barrier closes this tile
    }

    // ---- Epilogue: normalize and store (B,H,S,D) ----
    float inv0 = 1.0f / (sumA[0] + sumB[0]);
    float inv1 = 1.0f / (sumA[2] + sumB[2]);
    float* o0 = out + ((size_t)bh * S_ + (m0 + rl0)) * D_;
    float* o1 = out + ((size_t)bh * S_ + (m0 + rl0 + 8)) * D_;
#pragma unroll
    for (int nf = 0; nf < 16; nf++) {
        int c = nf * 8 + 2 * t4;
        *(float2*)(o0 + c) = make_float2(oacc[nf][0] * inv0, oacc[nf][1] * inv0);
        *(float2*)(o1 + c) = make_float2(oacc[nf][2] * inv1, oacc[nf][3] * inv1);
    }
}

// ---------------------------------------------------------------------------
// Flag reset for graph replay (runs after the fused kernel each call).
// ---------------------------------------------------------------------------
__global__ void reset_flags_kernel() {
    int i = threadIdx.x;
#pragma unroll
    for (int j = 0; j < NUNITS / 256; j++)
        g_flag[i + j * 256] = 0;
}

// ---------------------------------------------------------------------------
extern "C" void kernel_launch(void* const* d_in, const int* in_sizes, int n_in,
                              void* d_out, int out_size) {
    const float* q     = (const float*)d_in[0];
    const float* k     = (const float*)d_in[1];
    const float* v     = (const float*)d_in[2];
    const float* freqs = (const float*)d_in[3];
    float* out = (float*)d_out;
    (void)in_sizes; (void)n_in; (void)out_size;

    cudaFuncSetAttribute(fused_kernel,
                         cudaFuncAttributeMaxDynamicSharedMemorySize, SMEM_BYTES);

    fused_kernel<<<NPREP + BH_ * (S_ / BM), NTHREADS, SMEM_BYTES>>>(
        out, q, k, v, freqs);
    reset_flags_kernel<<<1, 256>>>();
}

// round 16
// speedup vs baseline: 1.3023x; 1.3023x over previous
#include <cuda_runtime.h>
#include <cuda_fp16.h>
#include <cstdint>

// ---------------------------------------------------------------------------
// PatternCWanRoPE R16: R14 config (best: 129.8us) + warp-local Q staging
// (one fewer CTA barrier; warps start independently) + streaming epilogue.
//   - kv_prep kernel: RoPE(K) + fp16 convert of K,V -> (B,H,S,D) scratch.
//   - attn kernel: fp16 warp-MMA FA (m16n8k16), Q RoPE fused in-kernel,
//     ldmatrix everywhere, register P-pass, cp.async double buffering,
//     single barrier per tile, f16x2 exp, MMA row-sums, alpha-skip.
//   q,k,v : (B=2, S=2048, H=16, D=128) fp32   freqs : (1,S,1,D)
//   out   : (B,H,S,D) fp32
// ---------------------------------------------------------------------------

#define B_ 2
#define S_ 2048
#define H_ 16
#define D_ 128
#define BH_ 32

#define BM 64
#define BN 64
#define NTHREADS 128

#define KPITCH_B 272              // 136 halves/row (128 data + 8 pad); 17x16B
#define TILE_B   (64 * KPITCH_B)  // 17408 bytes per K or V tile
#define OFF_K0   0
#define OFF_K1   TILE_B
#define OFF_V0   (2 * TILE_B)
#define OFF_V1   (3 * TILE_B)     // ALSO the Q staging area before cp(1)
#define SMEM_BYTES (4 * TILE_B)   // 69632

#define ONES_H2 0x3C003C00u       // half2(1.0, 1.0)

// fp16 scratch in (B,H,S,D): rope'd K, V. (Q never round-trips.)
__device__ __half g_k[(size_t)BH_ * S_ * D_];
__device__ __half g_v[(size_t)BH_ * S_ * D_];

// ---------------------------------------------------------------------------
__device__ __forceinline__ uint32_t smem_u32(const void* p) {
    uint32_t a;
    asm("{ .reg .u64 t; cvta.to.shared.u64 t, %1; cvt.u32.u64 %0, t; }"
        : "=r"(a) : "l"(p));
    return a;
}
__device__ __forceinline__ float fast_exp2(float x) {
    float y; asm("ex2.approx.f32 %0, %1;" : "=f"(y) : "f"(x));
    return y;
}
__device__ __forceinline__ uint32_t ex2_h2(uint32_t x) {
    uint32_t y; asm("ex2.approx.f16x2 %0, %1;" : "=r"(y) : "r"(x));
    return y;
}
__device__ __forceinline__ uint32_t h2pack(float a, float b) {
    __half2 h = __floats2half2_rn(a, b);
    return *reinterpret_cast<uint32_t*>(&h);
}
__device__ __forceinline__ void ldsm_x4(uint32_t r[4], uint32_t a) {
    asm volatile("ldmatrix.sync.aligned.m8n8.x4.shared.b16 {%0,%1,%2,%3}, [%4];"
                 : "=r"(r[0]), "=r"(r[1]), "=r"(r[2]), "=r"(r[3]) : "r"(a));
}
__device__ __forceinline__ void ldsm_x4_t(uint32_t r[4], uint32_t a) {
    asm volatile("ldmatrix.sync.aligned.m8n8.x4.trans.shared.b16 {%0,%1,%2,%3}, [%4];"
                 : "=r"(r[0]), "=r"(r[1]), "=r"(r[2]), "=r"(r[3]) : "r"(a));
}
__device__ __forceinline__ void mma_f16(float c[4], const uint32_t a[4],
                                        uint32_t b0, uint32_t b1) {
    asm volatile(
        "mma.sync.aligned.m16n8k16.row.col.f32.f16.f16.f32 "
        "{%0,%1,%2,%3}, {%4,%5,%6,%7}, {%8,%9}, {%0,%1,%2,%3};\n"
        : "+f"(c[0]), "+f"(c[1]), "+f"(c[2]), "+f"(c[3])
        : "r"(a[0]), "r"(a[1]), "r"(a[2]), "r"(a[3]), "r"(b0), "r"(b1));
}
__device__ __forceinline__ void stcs_f2(float* p, float2 v) {
    asm volatile("st.global.cs.v2.f32 [%0], {%1, %2};"
                 :: "l"(p), "f"(v.x), "f"(v.y) : "memory");
}
#define CP_COMMIT() asm volatile("cp.async.commit_group;" ::: "memory")
#define CP_WAIT0()  asm volatile("cp.async.wait_group 0;" ::: "memory")

// Prefetch one 64x128 fp16 K tile + V tile into SMEM buffers (one group).
__device__ __forceinline__ void cp_tile(const __half* __restrict__ Kg,
                                        const __half* __restrict__ Vg,
                                        uint32_t kbuf, uint32_t vbuf,
                                        int n0, int tid) {
#pragma unroll
    for (int i = 0; i < 8; i++) {
        int idx = tid + i * 128;
        int r = idx >> 4, c = idx & 15;
        uint32_t d = (uint32_t)(r * KPITCH_B + c * 16);
        asm volatile("cp.async.cg.shared.global [%0], [%1], 16;"
                     :: "r"(kbuf + d), "l"(Kg + (size_t)(n0 + r) * D_ + c * 8));
        asm volatile("cp.async.cg.shared.global [%0], [%1], 16;"
                     :: "r"(vbuf + d), "l"(Vg + (size_t)(n0 + r) * D_ + c * 8));
    }
    CP_COMMIT();
}

// ---------------------------------------------------------------------------
// Prologue: RoPE(k) + copy v, fp16 convert, (B,S,H,D)->(B,H,S,D).
// 8 halves (4 interleaved pairs) per thread; streaming loads.
// ---------------------------------------------------------------------------
__global__ void kv_prep_kernel(const float* __restrict__ k,
                               const float* __restrict__ v,
                               const float* __restrict__ freqs) {
    int pid = blockIdx.x * blockDim.x + threadIdx.x;
    int d8 = pid & 15;               // 16 groups of 8 elements
    int h  = (pid >> 4) & (H_ - 1);
    int s  = (pid >> 8) & (S_ - 1);
    int b  = pid >> 19;

    size_t in_off  = ((((size_t)b * S_ + s) * H_ + h) * D_) + 8 * d8;
    size_t f_off   = (size_t)s * D_ + 8 * d8;
    size_t out_off = ((((size_t)b * H_ + h) * S_ + s) * D_) + 8 * d8;

    float4 f0 = *(const float4*)(freqs + f_off);
    float4 f1 = *(const float4*)(freqs + f_off + 4);
    float4 k0 = __ldcs((const float4*)(k + in_off));
    float4 k1 = __ldcs((const float4*)(k + in_off + 4));
    float4 v0 = __ldcs((const float4*)(v + in_off));
    float4 v1 = __ldcs((const float4*)(v + in_off + 4));

    uint4 ok, ov;
    ok.x = h2pack(f0.x * k0.x - f0.y * k0.y, f0.y * k0.x + f0.x * k0.y);
    ok.y = h2pack(f0.z * k0.z - f0.w * k0.w, f0.w * k0.z + f0.z * k0.w);
    ok.z = h2pack(f1.x * k1.x - f1.y * k1.y, f1.y * k1.x + f1.x * k1.y);
    ok.w = h2pack(f1.z * k1.z - f1.w * k1.w, f1.w * k1.z + f1.z * k1.w);
    ov.x = h2pack(v0.x, v0.y);
    ov.y = h2pack(v0.z, v0.w);
    ov.z = h2pack(v1.x, v1.y);
    ov.w = h2pack(v1.z, v1.w);

    *(uint4*)(g_k + out_off) = ok;
    *(uint4*)(g_v + out_off) = ov;
}

// ---------------------------------------------------------------------------
// Flash attention. grid = (bh, q-tile [reversed]). 4 warps; warp w owns
// q rows [16w, 16w+16). ONE __syncthreads per tile. Q RoPE fused, warp-local.
// ---------------------------------------------------------------------------
__global__ void __launch_bounds__(NTHREADS, 2)
attn_kernel(float* __restrict__ out,
            const float* __restrict__ qf,
            const float* __restrict__ fr) {
    extern __shared__ __align__(16) char smem[];
    const uint32_t sb = smem_u32(smem);

    const int bh = blockIdx.x;
    const int qt = (int)(gridDim.y - 1) - (int)blockIdx.y;  // long rows first
    const int m0 = qt * BM;
    const int tid  = threadIdx.x;
    const int warp = tid >> 5;
    const int lane = tid & 31;
    const int g  = lane >> 2;
    const int t4 = lane & 3;
    const int b  = bh >> 4, h = bh & 15;

    const __half* Kg = g_k + (size_t)bh * S_ * D_;
    const __half* Vg = g_v + (size_t)bh * S_ * D_;

    // Kick off tile 0 prefetch (K0/V0) first; its latency hides Q prep.
    cp_tile(Kg, Vg, sb + OFF_K0, sb + OFF_V0, 0, tid);

    // ---- Q RoPE fused, WARP-LOCAL: warp w stages rows 16w..16w+15 of the
    //      q tile into V1 and reads back only those rows -> __syncwarp only.
    //      The loop-top __syncthreads (iter 0) still orders all V1 reads
    //      before cp(1) overwrites the buffer. ----
    {
        const float QS = 0.08838834764831845f * 1.4426950408889634f;
#pragma unroll
        for (int i = 0; i < 8; i++) {
            int r  = warp * 16 + 2 * i + (lane >> 4);   // warp-owned row
            int c8 = lane & 15;
            size_t qoff = ((((size_t)b * S_ + (m0 + r)) * H_ + h) * D_) + c8 * 8;
            size_t foff = (size_t)(m0 + r) * D_ + c8 * 8;
            float4 x0 = __ldcs((const float4*)(qf + qoff));
            float4 x1 = __ldcs((const float4*)(qf + qoff + 4));
            float4 f0 = *(const float4*)(fr + foff);
            float4 f1 = *(const float4*)(fr + foff + 4);
            uint4 o;
            o.x = h2pack((f0.x * x0.x - f0.y * x0.y) * QS,
                         (f0.y * x0.x + f0.x * x0.y) * QS);
            o.y = h2pack((f0.z * x0.z - f0.w * x0.w) * QS,
                         (f0.w * x0.z + f0.z * x0.w) * QS);
            o.z = h2pack((f1.x * x1.x - f1.y * x1.y) * QS,
                         (f1.y * x1.x + f1.x * x1.y) * QS);
            o.w = h2pack((f1.z * x1.z - f1.w * x1.w) * QS,
                         (f1.w * x1.z + f1.z * x1.w) * QS);
            *(uint4*)(smem + OFF_V1 + r * KPITCH_B + c8 * 16) = o;
        }
    }
    __syncwarp();   // warp-private staging -> warp-private ldsm below

    const uint32_t qaddr = sb + OFF_V1 + (warp * 16 + (lane & 15)) * KPITCH_B
                         + (lane >> 4) * 16;
    uint32_t qa[8][4];
#pragma unroll
    for (int kfr = 0; kfr < 8; kfr++) ldsm_x4(qa[kfr], qaddr + kfr * 32);

    // per-thread ldmatrix lane offsets (within a K / V tile)
    const uint32_t koff = ((lane >> 4) * 8 + (lane & 7)) * KPITCH_B
                        + ((lane >> 3) & 1) * 16;
    const uint32_t voff = (((lane >> 3) & 1) * 8 + (lane & 7)) * KPITCH_B
                        + (lane >> 4) * 16;

    float oacc[16][4];
#pragma unroll
    for (int i = 0; i < 16; i++) {
        oacc[i][0] = 0.f; oacc[i][1] = 0.f; oacc[i][2] = 0.f; oacc[i][3] = 0.f;
    }
    float sumA[4] = {0.f, 0.f, 0.f, 0.f};   // row sums via mma-with-ones
    float sumB[4] = {0.f, 0.f, 0.f, 0.f};   // (two accumulators: RAW dist 2)
    const int rl0 = warp * 16 + g;
    float mrow0 = -1e30f, mrow1 = -1e30f;   // running row max (log2 space)

    const int ntiles = qt + 1;
    for (int t = 0; t < ntiles; t++) {
        const uint32_t kb   = (t & 1) ? OFF_K1 : OFF_K0;
        const uint32_t vb_o = (t & 1) ? OFF_V1 : OFF_V0;

        // ---- Single barrier point per tile ----
        CP_WAIT0();
        __syncthreads();
        if (t + 1 < ntiles)
            cp_tile(Kg, Vg, sb + ((t & 1) ? OFF_K0 : OFF_K1),
                    sb + ((t & 1) ? OFF_V0 : OFF_V1), (t + 1) * BN, tid);

        const uint32_t kbase = sb + kb + koff;
        const uint32_t vbase = sb + vb_o + voff;

        // ---- S = Q K^T : kf OUTER so each sacc's RAW distance is 8 MMAs ----
        float sacc[8][4];
#pragma unroll
        for (int i = 0; i < 8; i++) {
            sacc[i][0] = 0.f; sacc[i][1] = 0.f; sacc[i][2] = 0.f; sacc[i][3] = 0.f;
        }
#pragma unroll
        for (int kfr = 0; kfr < 8; kfr++) {
#pragma unroll
            for (int np = 0; np < 4; np++) {
                uint32_t bfr[4];
                ldsm_x4(bfr, kbase + np * (16 * KPITCH_B) + kfr * 32);
                mma_f16(sacc[2 * np],     qa[kfr], bfr[0], bfr[1]);
                mma_f16(sacc[2 * np + 1], qa[kfr], bfr[2], bfr[3]);
            }
        }

        // ---- Causal mask (diagonal tile only) ----
        if (t == qt) {
#pragma unroll
            for (int nf = 0; nf < 8; nf++) {
                int c0 = nf * 8 + 2 * t4;
                if (c0     > rl0)     sacc[nf][0] = -1e30f;
                if (c0 + 1 > rl0)     sacc[nf][1] = -1e30f;
                if (c0     > rl0 + 8) sacc[nf][2] = -1e30f;
                if (c0 + 1 > rl0 + 8) sacc[nf][3] = -1e30f;
            }
        }

        // ---- Online softmax: row max via quad shuffle ----
        float tm0 = -1e30f, tm1 = -1e30f;
#pragma unroll
        for (int nf = 0; nf < 8; nf++) {
            tm0 = fmaxf(tm0, fmaxf(sacc[nf][0], sacc[nf][1]));
            tm1 = fmaxf(tm1, fmaxf(sacc[nf][2], sacc[nf][3]));
        }
        tm0 = fmaxf(tm0, __shfl_xor_sync(0xffffffffu, tm0, 1));
        tm0 = fmaxf(tm0, __shfl_xor_sync(0xffffffffu, tm0, 2));
        tm1 = fmaxf(tm1, __shfl_xor_sync(0xffffffffu, tm1, 1));
        tm1 = fmaxf(tm1, __shfl_xor_sync(0xffffffffu, tm1, 2));

        // Alpha-skip: rescale O / sums only when the running max increases.
        if (tm0 > mrow0 || tm1 > mrow1) {
            float mn0 = fmaxf(mrow0, tm0);
            float mn1 = fmaxf(mrow1, tm1);
            float alpha0 = fast_exp2(mrow0 - mn0);
            float alpha1 = fast_exp2(mrow1 - mn1);
            mrow0 = mn0; mrow1 = mn1;
            sumA[0] *= alpha0; sumA[2] *= alpha1;
            sumB[0] *= alpha0; sumB[2] *= alpha1;
#pragma unroll
            for (int nf = 0; nf < 16; nf++) {
                oacc[nf][0] *= alpha0; oacc[nf][1] *= alpha0;
                oacc[nf][2] *= alpha1; oacc[nf][3] *= alpha1;
            }
        }

        // ---- P = exp2(S - m): fp32 subtract, pack to half2, one MUFU per
        //      pair (ex2.approx.f16x2). Output IS the PV A-fragment. ----
        uint32_t paf[4][4];
#pragma unroll
        for (int kfr = 0; kfr < 4; kfr++) {
            paf[kfr][0] = ex2_h2(h2pack(sacc[2 * kfr][0] - mrow0,
                                        sacc[2 * kfr][1] - mrow0));
            paf[kfr][1] = ex2_h2(h2pack(sacc[2 * kfr][2] - mrow1,
                                        sacc[2 * kfr][3] - mrow1));
            paf[kfr][2] = ex2_h2(h2pack(sacc[2 * kfr + 1][0] - mrow0,
                                        sacc[2 * kfr + 1][1] - mrow0));
            paf[kfr][3] = ex2_h2(h2pack(sacc[2 * kfr + 1][2] - mrow1,
                                        sacc[2 * kfr + 1][3] - mrow1));
        }

        // ---- Row sums on the tensor pipe (interleaved accumulators) ----
        mma_f16(sumA, paf[0], ONES_H2, ONES_H2);
        mma_f16(sumB, paf[1], ONES_H2, ONES_H2);
        mma_f16(sumA, paf[2], ONES_H2, ONES_H2);
        mma_f16(sumB, paf[3], ONES_H2, ONES_H2);

        // ---- O += P V ----
#pragma unroll
        for (int kfr = 0; kfr < 4; kfr++) {
#pragma unroll
            for (int np = 0; np < 8; np++) {
                uint32_t vb[4];
                ldsm_x4_t(vb, vbase + kfr * (16 * KPITCH_B) + np * 32);
                mma_f16(oacc[2 * np],     paf[kfr], vb[0], vb[1]);
                mma_f16(oacc[2 * np + 1], paf[kfr], vb[2], vb[3]);
            }
        }
        // no trailing barrier: next iteration's top barrier closes this tile
    }

    // ---- Epilogue: normalize and store (B,H,S,D); streaming (not re-read) ----
    float inv0 = 1.0f / (sumA[0] + sumB[0]);
    float inv1 = 1.0f / (sumA[2] + sumB[2]);
    float* o0 = out + ((size_t)bh * S_ + (m0 + rl0)) * D_;
    float* o1 = out + ((size_t)bh * S_ + (m0 + rl0 + 8)) * D_;
#pragma unroll
    for (int nf = 0; nf < 16; nf++) {
        int c = nf * 8 + 2 * t4;
        stcs_f2(o0 + c, make_float2(oacc[nf][0] * inv0, oacc[nf][1] * inv0));
        stcs_f2(o1 + c, make_float2(oacc[nf][2] * inv1, oacc[nf][3] * inv1));
    }
}

// ---------------------------------------------------------------------------
extern "C" void kernel_launch(void* const* d_in, const int* in_sizes, int n_in,
                              void* d_out, int out_size) {
    const float* q     = (const float*)d_in[0];
    const float* k     = (const float*)d_in[1];
    const float* v     = (const float*)d_in[2];
    const float* freqs = (const float*)d_in[3];
    float* out = (float*)d_out;
    (void)in_sizes; (void)n_in; (void)out_size;

    cudaFuncSetAttribute(attn_kernel,
                         cudaFuncAttributeMaxDynamicSharedMemorySize, SMEM_BYTES);

    const int TOTAL8 = B_ * S_ * H_ * (D_ / 8);   // 1,048,576 threads
    kv_prep_kernel<<<TOTAL8 / 256, 256>>>(k, v, freqs);

    dim3 grid(BH_, S_ / BM);
    attn_kernel<<<grid, NTHREADS, SMEM_BYTES>>>(out, q, freqs);
}